// round 9
// baseline (speedup 1.0000x reference)
#include <cuda_runtime.h>
#include <math.h>
#include <float.h>

// Problem constants (fixed by setup_inputs)
#define BB 4
#define CC 256
#define MM 1024
#define NN 16384
#define HH 224
#define WW 224
#define HWH (HH*WW)
#define KPOOL 4
#define OH (HH/KPOOL)   // 56
#define OW (WW/KPOOL)   // 56
#define PP (OH*OW)      // 3136 pool cells
#define GG 8            // locality-sort grid 8x8x8
#define GC (GG*GG*GG)   // 512 cells

// Scratch (zero-initialized at module load; every launch restores zeros)
__device__ float  g_xt[(size_t)BB * MM * CC];    // xyz_feats transposed [b][m][c] (4MB)
__device__ float  g_pool[(size_t)BB * PP * CC];  // pooled accumulator (12.8MB)
__device__ float  g_cnt[(size_t)BB * HWH];       // per-pixel point count (800KB)
__device__ int    g_ccnt[BB * GC];               // per-cell point count (must be 0 at entry)
__device__ int    g_pstart[BB * (GC + 1)];       // point CSR starts (rebuilt each launch)
__device__ int    g_pcur[BB * GC];               // scatter cursors (rebuilt each launch)
__device__ float4 g_pq[(size_t)BB * NN];         // points sorted by cell (x,y,z,bitcast pix)
__device__ float4 g_rec[(size_t)BB * NN];        // per-point records (packed idx, w0s,w1s,w2s)

// ---------------------------------------------------------------------------
// Bit-exact helpers (DO NOT TOUCH — these fix the discrete selection/binning)
// ---------------------------------------------------------------------------
__device__ __forceinline__ float norm3_ref(float x, float y, float z) {
    return __fadd_rn(__fadd_rn(__fmul_rn(x, x), __fmul_rn(y, y)), __fmul_rn(z, z));
}
// Projection row: NO-FMA ascending chain (matches XLA elementwise lowering)
__device__ __forceinline__ float proj_row(float k0, float k1, float k2,
                                          float x, float y, float z) {
    return __fadd_rn(__fadd_rn(__fmul_rn(k0, x), __fmul_rn(k1, y)), __fmul_rn(k2, z));
}
__device__ __forceinline__ int pixel_of(const float* __restrict__ Km,
                                        float px, float py, float pz) {
    float uz0 = proj_row(Km[0], Km[1], Km[2], px, py, pz);
    float uz1 = proj_row(Km[3], Km[4], Km[5], px, py, pz);
    float uz2 = proj_row(Km[6], Km[7], Km[8], px, py, pz);
    float zden = fmaxf(uz2, 1e-8f);
    float uf = floorf(__fdiv_rn(uz0, zden));
    float vf = floorf(__fdiv_rn(uz1, zden));
    int u = (int)fminf(fmaxf(uf, 0.0f), (float)(WW - 1));
    int v = (int)fminf(fmaxf(vf, 0.0f), (float)(HH - 1));
    return v * WW + u;
}
__device__ __forceinline__ float dist_exact(float px, float py, float pz, float pn,
                                            float4 c) {
    float dot = fmaf(pz, c.z, fmaf(py, c.y, __fmul_rn(px, c.x)));
    return __fsub_rn(__fadd_rn(pn, c.w), __fmul_rn(2.0f, dot));
}
__device__ __forceinline__ void red_add_v4(float* addr, float4 v) {
    asm volatile("red.global.add.v4.f32 [%0], {%1, %2, %3, %4};"
                 :: "l"(addr), "f"(v.x), "f"(v.y), "f"(v.z), "f"(v.w)
                 : "memory");
}
__device__ __forceinline__ int cell_coord(float x) {        // x,y in [0,1)
    return min(GG - 1, max(0, (int)(x * (float)GG)));
}
__device__ __forceinline__ int cell_coord_z(float z) {      // z in [0.5,1.5)
    return min(GG - 1, max(0, (int)((z - 0.5f) * (float)GG)));
}
__device__ __forceinline__ int cell_of(float x, float y, float z) {
    return (cell_coord_z(z) * GG + cell_coord(y)) * GG + cell_coord(x);
}

// ---------------------------------------------------------------------------
// Kernel 1: transpose xyz_feats [B][C][M] -> g_xt [B][M][C]
// ---------------------------------------------------------------------------
__global__ void k_transpose(const float* __restrict__ X) {
    __shared__ float tile[32][33];
    int b  = blockIdx.z;
    int m0 = blockIdx.x * 32;
    int c0 = blockIdx.y * 32;
    int tx = threadIdx.x, ty = threadIdx.y;  // block (32,8)
    #pragma unroll
    for (int k = 0; k < 32; k += 8)
        tile[ty + k][tx] = X[((size_t)b * CC + (c0 + ty + k)) * MM + (m0 + tx)];
    __syncthreads();
    #pragma unroll
    for (int k = 0; k < 32; k += 8)
        g_xt[((size_t)b * MM + (m0 + ty + k)) * CC + (c0 + tx)] = tile[tx][ty + k];
}

// ---------------------------------------------------------------------------
// Kernel 2: count points per 3D cell + per pixel. grid (8, BB), 256 thr.
// ---------------------------------------------------------------------------
__global__ void __launch_bounds__(256) k_pcount(
    const float* __restrict__ pts, const float* __restrict__ Km)
{
    int b = blockIdx.y;
    int t = blockIdx.x * 256 + threadIdx.x;    // 0..2047
    #pragma unroll
    for (int k = 0; k < NN / 2048; k++) {
        int n = k * 2048 + t;
        const float* p = &pts[((size_t)b * NN + n) * 3];
        float x = __ldg(&p[0]), y = __ldg(&p[1]), z = __ldg(&p[2]);
        atomicAdd(&g_ccnt[b * GC + cell_of(x, y, z)], 1);
        atomicAdd(&g_cnt[(size_t)b * HWH + pixel_of(Km, x, y, z)], 1.0f);
    }
}

// ---------------------------------------------------------------------------
// Kernel 3: scan cell counts -> CSR + cursors; zero g_ccnt. grid BB, 512 thr.
// ---------------------------------------------------------------------------
__global__ void __launch_bounds__(GC) k_pscan() {
    __shared__ int s[GC];
    int b = blockIdx.x;
    int t = threadIdx.x;
    s[t] = g_ccnt[b * GC + t];
    g_ccnt[b * GC + t] = 0;                   // restore zero invariant
    __syncthreads();
    for (int off = 1; off < GC; off <<= 1) {
        int add = (t >= off) ? s[t - off] : 0;
        __syncthreads();
        s[t] += add;
        __syncthreads();
    }
    int st = (t == 0) ? 0 : s[t - 1];
    g_pstart[b * (GC + 1) + t] = st;
    g_pcur[b * GC + t] = st;
    if (t == 0) g_pstart[b * (GC + 1) + GC] = NN;
}

// ---------------------------------------------------------------------------
// Kernel 4: scatter points into cell-sorted order. grid (8, BB), 256 thr.
// ---------------------------------------------------------------------------
__global__ void __launch_bounds__(256) k_pscatter(
    const float* __restrict__ pts, const float* __restrict__ Km)
{
    int b = blockIdx.y;
    int t = blockIdx.x * 256 + threadIdx.x;
    #pragma unroll
    for (int k = 0; k < NN / 2048; k++) {
        int n = k * 2048 + t;
        const float* p = &pts[((size_t)b * NN + n) * 3];
        float x = __ldg(&p[0]), y = __ldg(&p[1]), z = __ldg(&p[2]);
        int pix = pixel_of(Km, x, y, z);
        int pos = atomicAdd(&g_pcur[b * GC + cell_of(x, y, z)], 1);
        g_pq[(size_t)b * NN + pos] = make_float4(x, y, z, __int_as_float(pix));
    }
}

// ---------------------------------------------------------------------------
// Kernel 5: dense thread-per-point 3-NN over sorted points -> records.
// grid (NN/256, BB), 256 thr, smem = centers only.
// ---------------------------------------------------------------------------
__global__ void __launch_bounds__(256) k_knn(const float* __restrict__ ctr) {
    __shared__ float4 sc[MM];        // centers (x,y,z,|c|^2)  16KB
    int b   = blockIdx.y;
    int tid = threadIdx.x;

    for (int i = tid; i < MM; i += 256) {
        float x = ctr[((size_t)b * MM + i) * 3 + 0];
        float y = ctr[((size_t)b * MM + i) * 3 + 1];
        float z = ctr[((size_t)b * MM + i) * 3 + 2];
        sc[i] = make_float4(x, y, z, norm3_ref(x, y, z));
    }
    __syncthreads();

    int n = blockIdx.x * 256 + tid;
    float4 q = g_pq[(size_t)b * NN + n];
    float px = q.x, py = q.y, pz = q.z;
    int pix = __float_as_int(q.w);
    float pn = norm3_ref(px, py, pz);

    // dense top-3: strict-<, ascending m (ties -> earliest index)
    float d0 = FLT_MAX, d1 = FLT_MAX, d2 = FLT_MAX;
    int   i0 = 0, i1 = 0, i2 = 0;
    #pragma unroll 4
    for (int m = 0; m < MM; m++) {
        float d = dist_exact(px, py, pz, pn, sc[m]);
        if (d < d2) {
            if (d < d1) {
                d2 = d1; i2 = i1;
                if (d < d0) { d1 = d0; i1 = i0; d0 = d; i0 = m; }
                else        { d1 = d;  i1 = m; }
            } else { d2 = d; i2 = m; }
        }
    }

    float w0 = __fdiv_rn(1.0f, __fadd_rn(d0, 1e-8f));
    float w1 = __fdiv_rn(1.0f, __fadd_rn(d1, 1e-8f));
    float w2 = __fdiv_rn(1.0f, __fadd_rn(d2, 1e-8f));
    float ws = __fadd_rn(__fadd_rn(w0, w1), w2);
    w0 = __fdiv_rn(w0, ws); w1 = __fdiv_rn(w1, ws); w2 = __fdiv_rn(w2, ws);

    float cnt = g_cnt[(size_t)b * HWH + pix];
    float scale = __fdiv_rn(1.0f, cnt) * 0.0625f;

    int pk = i0 | (i1 << 10) | (i2 << 20);
    g_rec[(size_t)b * NN + n] =
        make_float4(__int_as_float(pk), w0 * scale, w1 * scale, w2 * scale);
}

// ---------------------------------------------------------------------------
// Kernel 6: warp-cooperative gather + v4 scatter (sorted order -> L1 reuse).
// grid (NN/256, BB), 256 thr, smem = staging only (8KB).
// ---------------------------------------------------------------------------
__global__ void __launch_bounds__(256) k_scatter() {
    __shared__ int4   stg_i[256];
    __shared__ float4 stg_w[256];

    int b    = blockIdx.y;
    int tid  = threadIdx.x;
    int lane = tid & 31;
    int n    = blockIdx.x * 256 + tid;

    float4 rec = g_rec[(size_t)b * NN + n];
    int pk  = __float_as_int(rec.x);
    int pix = __float_as_int(g_pq[(size_t)b * NN + n].w);
    int v = pix / WW, u = pix % WW;
    int cell = (v >> 2) * OW + (u >> 2);
    int dstBase = (b * PP + cell) * CC;

    stg_i[tid] = make_int4(pk & 1023, (pk >> 10) & 1023, (pk >> 20) & 1023, dstBase);
    stg_w[tid] = make_float4(rec.y, rec.z, rec.w, 0.0f);
    __syncwarp();

    const float4* xt4 = reinterpret_cast<const float4*>(g_xt);
    int wbase = tid & ~31;
    #pragma unroll 1
    for (int k = 0; k < 32; k++) {
        int4   si = stg_i[wbase + k];   // broadcast
        float4 sw = stg_w[wbase + k];
        const float4* r0 = xt4 + ((size_t)b * MM + si.x) * (CC / 4);
        const float4* r1 = xt4 + ((size_t)b * MM + si.y) * (CC / 4);
        const float4* r2 = xt4 + ((size_t)b * MM + si.z) * (CC / 4);
        float* dp = &g_pool[si.w];
        #pragma unroll
        for (int j = 0; j < 2; j++) {
            int c4 = j * 32 + lane;
            float4 a  = __ldg(&r0[c4]);
            float4 bq = __ldg(&r1[c4]);
            float4 cq = __ldg(&r2[c4]);
            float4 f;
            f.x = fmaf(sw.x, a.x, fmaf(sw.y, bq.x, sw.z * cq.x));
            f.y = fmaf(sw.x, a.y, fmaf(sw.y, bq.y, sw.z * cq.y));
            f.z = fmaf(sw.x, a.z, fmaf(sw.y, bq.z, sw.z * cq.z));
            f.w = fmaf(sw.x, a.w, fmaf(sw.y, bq.w, sw.z * cq.w));
            red_add_v4(dp + c4 * 4, f);
        }
    }
}

// ---------------------------------------------------------------------------
// Kernel 7: vectorized transpose g_pool [b][p][c] -> out [b][c][p] + clear.
// ---------------------------------------------------------------------------
__global__ void __launch_bounds__(256) k_pool_out(float* __restrict__ out) {
    __shared__ float tile[64][65];
    int b  = blockIdx.z;
    int c0 = blockIdx.y * 64;
    int p0 = blockIdx.x * 64;
    int tid = threadIdx.x;

    float4 v[4];
    #pragma unroll
    for (int r = 0; r < 4; r++) {
        int w = tid + 256 * r;
        int cell = w >> 4, c4 = w & 15;
        size_t idx = ((size_t)b * PP + p0 + cell) * CC + c0 + c4 * 4;
        v[r] = *reinterpret_cast<const float4*>(&g_pool[idx]);
    }
    const float4 z4 = make_float4(0.f, 0.f, 0.f, 0.f);
    #pragma unroll
    for (int r = 0; r < 4; r++) {
        int w = tid + 256 * r;
        int cell = w >> 4, c4 = w & 15;
        size_t idx = ((size_t)b * PP + p0 + cell) * CC + c0 + c4 * 4;
        *reinterpret_cast<float4*>(&g_pool[idx]) = z4;   // restore invariant
        tile[cell][c4 * 4 + 0] = v[r].x;
        tile[cell][c4 * 4 + 1] = v[r].y;
        tile[cell][c4 * 4 + 2] = v[r].z;
        tile[cell][c4 * 4 + 3] = v[r].w;
    }
    if (blockIdx.y == 0) {
        #pragma unroll
        for (int k = 0; k < 4; k++) {
            int i = blockIdx.x * 256 + tid + k * (49 * 256);
            g_cnt[(size_t)b * HWH + i] = 0.0f;   // 49*256*4 = 50176 = HWH
        }
    }
    __syncthreads();

    #pragma unroll
    for (int r = 0; r < 4; r++) {
        int w = tid + 256 * r;
        int c = w >> 4, p4 = w & 15;
        float4 f;
        f.x = tile[p4 * 4 + 0][c];
        f.y = tile[p4 * 4 + 1][c];
        f.z = tile[p4 * 4 + 2][c];
        f.w = tile[p4 * 4 + 3][c];
        *reinterpret_cast<float4*>(&out[((size_t)b * CC + c0 + c) * PP + p0 + p4 * 4]) = f;
    }
}

// ---------------------------------------------------------------------------
extern "C" void kernel_launch(void* const* d_in, const int* in_sizes, int n_in,
                              void* d_out, int out_size) {
    const float* feats = (const float*)d_in[0];  // [B][C][M]
    const float* pts   = (const float*)d_in[1];  // [B][N][3]
    const float* ctr   = (const float*)d_in[2];  // [B][M][3]
    const float* Km    = (const float*)d_in[3];  // [3][3]
    float* out = (float*)d_out;

    k_transpose<<<dim3(MM / 32, CC / 32, BB), dim3(32, 8)>>>(feats);
    k_pcount<<<dim3(8, BB), 256>>>(pts, Km);
    k_pscan<<<BB, GC>>>();
    k_pscatter<<<dim3(8, BB), 256>>>(pts, Km);
    k_knn<<<dim3(NN / 256, BB), 256>>>(ctr);
    k_scatter<<<dim3(NN / 256, BB), 256>>>();
    k_pool_out<<<dim3(PP / 64, CC / 64, BB), 256>>>(out);
}